// round 12
// baseline (speedup 1.0000x reference)
#include <cuda_runtime.h>

// out[t,b,i,e] = x[t,b,i] * W[i,e] + b[e];  T=8,B=64,D=512,E=256; k=t*B+b.
// out[(k*512 + i)*256 + e] = x[k*512+i] * W[i*256+e] + b[e]
//
// R10: 256-bit stores (st.global.cs.v8.f32, sm_100+). Warp = 32 lanes x 8
// floats = one full 1KB output row per store instruction. Halves store
// instruction/dispatch count vs STG.128; keeps .cs policy (sweep winner).
// Grid: x=i (512), y=chunk (8, 64 k each). Block 256 = 8 warps; each warp
// owns 8 k-rows.

#define D_DIM 512
#define E_DIM 256
#define E4    64
#define K_CHUNKS 8
#define ROWS_PER_WARP 8

__global__ __launch_bounds__(256) void dense_embed_kernel(
    const float* __restrict__ x,    // [512 * 512]
    const float4* __restrict__ W4,  // [512 * 64]
    const float4* __restrict__ b4,  // [64]
    float* __restrict__ out)        // [512 * 512 * 256]
{
    const unsigned i    = blockIdx.x;                 // 0..511
    const unsigned lane = threadIdx.x & 31;           // e8 index: e = lane*8..+7
    const unsigned warp = threadIdx.x >> 5;           // 0..7
    const unsigned k0   = blockIdx.y * 64 + warp * ROWS_PER_WARP;

    // Per-thread invariants: 8 W floats + 8 b floats, loaded once.
    const float4 w0 = __ldg(&W4[i * E4 + lane * 2]);
    const float4 w1 = __ldg(&W4[i * E4 + lane * 2 + 1]);
    const float4 c0 = __ldg(&b4[lane * 2]);
    const float4 c1 = __ldg(&b4[lane * 2 + 1]);

    const float* xp = x + (size_t)k0 * D_DIM + i;
    float* op = out + ((size_t)k0 * D_DIM + i) * E_DIM + lane * 8;

    // Batch the 8 x loads (independent, fully overlapped).
    float xv[ROWS_PER_WARP];
    #pragma unroll
    for (int r = 0; r < ROWS_PER_WARP; r++)
        xv[r] = __ldg(&xp[(size_t)r * D_DIM]);

    // 8 back-to-back FMA8 + STG.256 (.cs). Each warp store = 1KB contiguous.
    #pragma unroll
    for (int r = 0; r < ROWS_PER_WARP; r++) {
        float o0 = fmaf(xv[r], w0.x, c0.x);
        float o1 = fmaf(xv[r], w0.y, c0.y);
        float o2 = fmaf(xv[r], w0.z, c0.z);
        float o3 = fmaf(xv[r], w0.w, c0.w);
        float o4 = fmaf(xv[r], w1.x, c1.x);
        float o5 = fmaf(xv[r], w1.y, c1.y);
        float o6 = fmaf(xv[r], w1.z, c1.z);
        float o7 = fmaf(xv[r], w1.w, c1.w);
        asm volatile(
            "st.global.cs.v8.f32 [%0], {%1,%2,%3,%4,%5,%6,%7,%8};"
            :: "l"(op + (size_t)r * D_DIM * E_DIM),
               "f"(o0), "f"(o1), "f"(o2), "f"(o3),
               "f"(o4), "f"(o5), "f"(o6), "f"(o7)
            : "memory");
    }
}

extern "C" void kernel_launch(void* const* d_in, const int* in_sizes, int n_in,
                              void* d_out, int out_size) {
    const float*  x  = (const float*)d_in[0];
    const float4* W4 = (const float4*)d_in[1];
    const float4* b4 = (const float4*)d_in[2];
    float* out = (float*)d_out;

    dim3 grid(D_DIM, K_CHUNKS);   // 512 x 8 = 4096 blocks
    dense_embed_kernel<<<grid, 256>>>(x, W4, b4, out);
}

// round 13
// speedup vs baseline: 1.0051x; 1.0051x over previous
#include <cuda_runtime.h>
#include <cstdint>

// out[t,b,i,e] = x[t,b,i]*W[i,e] + b[e];  T=8,B=64,D=512,E=256; k=t*B+b.
// R12: TMA bulk-store path (best in-window drain, R9: 39.7us) with in-block
// double buffering to kill R9's compute->drain serialization.
// Block: fixed i, 64 k-rows as 4 tiles of 16 rows. Two 16KB SMEM buffers;
// tile t+1 compute overlaps tile t bulk drain (wait_group 1 recycle gate).

#define D_DIM 512
#define E4    64
#define TILE_ROWS 16
#define TILES 4
#define K_PER_BLK (TILE_ROWS * TILES)   // 64
#define K_CHUNKS 8                       // 512 / 64

__global__ __launch_bounds__(256) void dense_embed_kernel(
    const float* __restrict__ x,    // [512 * 512]
    const float4* __restrict__ W4,  // [512 * 64]
    const float4* __restrict__ b4,  // [64]
    float4* __restrict__ out4)      // [512 * 512 * 64]
{
    __shared__ __align__(128) float4 buf[2][TILE_ROWS * E4];   // 2 x 16KB

    const unsigned tid = threadIdx.x;
    const unsigned i   = blockIdx.x;               // 0..511
    const unsigned k0  = blockIdx.y * K_PER_BLK;   // 0,64,..,448
    const unsigned e4  = tid & (E4 - 1);           // 0..63
    const unsigned kg  = tid >> 6;                 // 0..3 (4 rows each)

    const float4 w  = __ldg(&W4[i * E4 + e4]);
    const float4 bb = __ldg(&b4[e4]);

    #pragma unroll
    for (int t = 0; t < TILES; ++t) {
        if (t >= 2) {
            // Buffer t&1 was committed at tile t-2; allow only the t-1 group
            // to remain in flight before overwriting it.
            if (tid < TILE_ROWS)
                asm volatile("cp.async.bulk.wait_group 1;" ::: "memory");
            __syncthreads();
        }
        float4* bp = buf[t & 1];
        const unsigned kbase = k0 + t * TILE_ROWS;

        // 4 batched uniform x loads, then 4 FMA4 + conflict-free STS.
        float xv[4];
        #pragma unroll
        for (int r = 0; r < 4; ++r)
            xv[r] = __ldg(&x[(size_t)(kbase + kg * 4 + r) * D_DIM + i]);
        #pragma unroll
        for (int r = 0; r < 4; ++r) {
            float4 o;
            o.x = fmaf(xv[r], w.x, bb.x);
            o.y = fmaf(xv[r], w.y, bb.y);
            o.z = fmaf(xv[r], w.z, bb.z);
            o.w = fmaf(xv[r], w.w, bb.w);
            bp[(kg * 4 + r) * E4 + e4] = o;
        }
        __syncthreads();

        // 16 lanes each drain one 1KB row as a bulk copy (one group per tile
        // per issuing thread; bulk_group state is per-thread).
        if (tid < TILE_ROWS) {
            asm volatile("fence.proxy.async.shared::cta;" ::: "memory");
            float4* dst = out4 + ((size_t)(kbase + tid) * D_DIM + i) * E4;
            uint32_t src;
            asm("{ .reg .u64 tt; cvta.to.shared.u64 tt, %1; cvt.u32.u64 %0, tt; }"
                : "=r"(src) : "l"(&bp[tid * E4]));
            asm volatile(
                "cp.async.bulk.global.shared::cta.bulk_group [%0], [%1], %2;"
                :: "l"(dst), "r"(src), "n"(E4 * 16) : "memory");
            asm volatile("cp.async.bulk.commit_group;" ::: "memory");
        }
    }

    // Block may not exit with bulk reads of its SMEM in flight.
    if (tid < TILE_ROWS)
        asm volatile("cp.async.bulk.wait_group 0;" ::: "memory");
}

extern "C" void kernel_launch(void* const* d_in, const int* in_sizes, int n_in,
                              void* d_out, int out_size) {
    const float*  x  = (const float*)d_in[0];
    const float4* W4 = (const float4*)d_in[1];
    const float4* b4 = (const float4*)d_in[2];
    float4* out4 = (float4*)d_out;

    dim3 grid(D_DIM, K_CHUNKS);   // 512 x 8 = 4096 blocks
    dense_embed_kernel<<<grid, 256>>>(x, W4, b4, out4);
}

// round 15
// speedup vs baseline: 1.0556x; 1.0502x over previous
#include <cuda_runtime.h>

// out[t,b,i,e] = x[t,b,i] * W[i,e] + b[e]
// T=8, B=64, D=512, E=256. k = t*B+b in [0,512).
// out4[(k*512 + i)*64 + e4] = x[k*512 + i] * W4[i*64 + e4] + b4[e4]
//
// FINAL (revert to R5, best wall 41.57us): grid x=i (512), y=k-chunk (8).
// Block 256 thr = 4 kg x 64 e4. W/b register-cached; 16 batched uniform
// x-loads (MLP=16); 16 back-to-back FMA4 + __stcs STG.128.
//
// Plateau evidence across 8 variants (policy sweep stcs/wt/wb, MLP batching,
// schedule order, STG.256, TMA bulk single/double-buffered): all 40.4-41.5us
// in-window, DRAM 64.0-66.8%, sustained write rate ~6.45 TB/s (~80% of 8TB/s
// spec) == pure-write HBM3e ceiling. No SM-side metric saturated anywhere;
// structurally different store paths converge to the same drain rate.

#define D_DIM 512
#define E4    64
#define K_CHUNKS 8
#define K_PER_CHUNK 64
#define KK 16

__global__ __launch_bounds__(256) void dense_embed_kernel(
    const float* __restrict__ x,    // [512 * 512]
    const float4* __restrict__ W4,  // [512 * 64]
    const float4* __restrict__ b4,  // [64]
    float4* __restrict__ out4)      // [512 * 512 * 64]
{
    const unsigned i  = blockIdx.x;               // 0..511
    const unsigned e4 = threadIdx.x & (E4 - 1);   // 0..63
    const unsigned kg = threadIdx.x >> 6;         // 0..3
    const unsigned k0 = blockIdx.y * K_PER_CHUNK + kg * KK;

    // Per-thread invariants
    const float4 w  = __ldg(&W4[i * E4 + e4]);
    const float4 bb = __ldg(&b4[e4]);

    const float* xp = x + (size_t)k0 * D_DIM + i;
    float4* op = out4 + ((size_t)k0 * D_DIM + i) * E4 + e4;

    // Batch all 16 x loads up front — independent, fully overlapped.
    float xv[KK];
    #pragma unroll
    for (int kk = 0; kk < KK; kk++)
        xv[kk] = __ldg(&xp[(size_t)kk * D_DIM]);

    // Pure store stream: 16 back-to-back FMA4 + evict-first STG.128.
    #pragma unroll
    for (int kk = 0; kk < KK; kk++) {
        float4 o;
        o.x = fmaf(xv[kk], w.x, bb.x);
        o.y = fmaf(xv[kk], w.y, bb.y);
        o.z = fmaf(xv[kk], w.z, bb.z);
        o.w = fmaf(xv[kk], w.w, bb.w);
        __stcs(&op[(size_t)kk * D_DIM * E4], o);
    }
}

extern "C" void kernel_launch(void* const* d_in, const int* in_sizes, int n_in,
                              void* d_out, int out_size) {
    const float*  x  = (const float*)d_in[0];
    const float4* W4 = (const float4*)d_in[1];
    const float4* b4 = (const float4*)d_in[2];
    float4* out4 = (float4*)d_out;

    dim3 grid(D_DIM, K_CHUNKS);   // 512 x 8 = 4096 blocks
    dense_embed_kernel<<<grid, 256>>>(x, W4, b4, out4);
}